// round 4
// baseline (speedup 1.0000x reference)
#include <cuda_runtime.h>
#include <cuda_bf16.h>
#include <cstdint>

// Problem constants (fixed-shape benchmark)
#define B 8
#define C 256
#define H 128
#define W 128
#define HW (H * W)
#define CO 21
#define NSEG (B * CO)
#define EPS 1e-12f

#define N_FEAT (B * C * H * W)      // 33554432
#define N_OUT  (B * CO * H * W)     // 2752512
#define N_LAB  (B * H * W)          // 131072

// ---------------- scratch (device globals; no allocation) ----------------
__device__ unsigned char g_seg[B * HW];     // per-pixel class id (0..20)
__device__ float g_cnt[NSEG];               // per-segment pixel count (unique writer)
__device__ float g_sum_cur[NSEG * C];       // segment sums (features)
__device__ float g_sum_ref[NSEG * C];       // segment sums (features_old)
__device__ float g_k;                       // number of valid prototypes
__device__ float g_sq;                      // sum of squared gram diffs (masked)
__device__ unsigned int g_ticket;           // last-block finalize ticket

// ---------------- kernel 1: pseudo labels (+ zero scalars) ----------------
// grid: (HW/256, B), block: 256
__global__ void k_pseudo(const float* __restrict__ outputs_old,
                         const int* __restrict__ labels,
                         const int* __restrict__ num_old_ptr) {
    if (blockIdx.x == 0 && blockIdx.y == 0 && threadIdx.x == 0) {
        g_sq = 0.0f; g_k = 0.0f; g_ticket = 0u;
    }
    int b = blockIdx.y;
    int p = blockIdx.x * 256 + threadIdx.x;
    int nold = *num_old_ptr;

    const float* oo = outputs_old + (size_t)b * CO * HW + p;
    float best = oo[0];
    int bi = 0;
#pragma unroll
    for (int c = 1; c < CO; ++c) {
        float v = __ldg(oo + (size_t)c * HW);
        if (v > best) { best = v; bi = c; }
    }
    int lab = labels[b * HW + p];
    int cls = (lab < nold) ? bi : 0;
    g_seg[b * HW + p] = (unsigned char)cls;
}

// ---------------- kernel 2: segment sums + counts ----------------
// grid: (C+1, B), block: 256.
//   c <  C : one block owns one (b,c) plane -> conflict-free smem scatter, plain stores
//   c == C : histogram block: per-image counts -> g_cnt (unique writer) + g_k
__global__ __launch_bounds__(256) void k_segsum(const float* __restrict__ features,
                                                const float* __restrict__ features_old) {
    __shared__ float acc_cur[CO * 256];
    __shared__ float acc_ref[CO * 256];
    int tid = threadIdx.x;
    int c = blockIdx.x;
    int b = blockIdx.y;

    const uchar4* __restrict__ sg = (const uchar4*)(g_seg + (size_t)b * HW);

    if (c == C) {
        // ---- histogram block ----
        __shared__ int hist[CO];
        if (tid < CO) hist[tid] = 0;
        __syncthreads();
#pragma unroll 4
        for (int it = 0; it < 16; ++it) {
            uchar4 s4 = sg[it * 256 + tid];
            atomicAdd(&hist[(int)s4.x], 1);
            atomicAdd(&hist[(int)s4.y], 1);
            atomicAdd(&hist[(int)s4.z], 1);
            atomicAdd(&hist[(int)s4.w], 1);
        }
        __syncthreads();
        if (tid < CO) g_cnt[b * CO + tid] = (float)hist[tid];
        if (tid == 0) {
            float kk = 0.0f;
            for (int s = 1; s < CO; ++s) if (hist[s] > 0) kk += 1.0f;
            atomicAdd(&g_k, kk);
        }
        return;
    }

    // ---- accumulation block ----
#pragma unroll
    for (int s = 0; s < CO; ++s) {
        acc_cur[s * 256 + tid] = 0.0f;
        acc_ref[s * 256 + tid] = 0.0f;
    }
    __syncthreads();

    const float4* __restrict__ fc = (const float4*)(features     + ((size_t)b * C + c) * HW);
    const float4* __restrict__ fr = (const float4*)(features_old + ((size_t)b * C + c) * HW);

#pragma unroll 4
    for (int it = 0; it < 16; ++it) {
        int idx = it * 256 + tid;          // float4 index, 0..4095
        float4 xc = __ldg(fc + idx);
        float4 xr = __ldg(fr + idx);
        uchar4 s4 = sg[idx];
        acc_cur[(int)s4.x * 256 + tid] += xc.x;
        acc_cur[(int)s4.y * 256 + tid] += xc.y;
        acc_cur[(int)s4.z * 256 + tid] += xc.z;
        acc_cur[(int)s4.w * 256 + tid] += xc.w;
        acc_ref[(int)s4.x * 256 + tid] += xr.x;
        acc_ref[(int)s4.y * 256 + tid] += xr.y;
        acc_ref[(int)s4.z * 256 + tid] += xr.z;
        acc_ref[(int)s4.w * 256 + tid] += xr.w;
    }
    __syncthreads();

    int w = tid >> 5, l = tid & 31;
    for (int s = w; s < CO; s += 8) {
        float vc = 0.0f, vr = 0.0f;
#pragma unroll
        for (int q = l; q < 256; q += 32) {
            vc += acc_cur[s * 256 + q];
            vr += acc_ref[s * 256 + q];
        }
#pragma unroll
        for (int o = 16; o; o >>= 1) {
            vc += __shfl_down_sync(0xFFFFFFFFu, vc, o);
            vr += __shfl_down_sync(0xFFFFFFFFu, vr, o);
        }
        if (l == 0) {
            g_sum_cur[(b * CO + s) * C + c] = vc;
            g_sum_ref[(b * CO + s) * C + c] = vr;
        }
    }
}

// ---------------- kernel 3: Gram-difference MSE + finalize ----------------
// grid: NSEG, block: 256. Norms recomputed from raw sums (denom cancels:
// p = sum / max(|sum|, eps*denom)). Last block writes the scalar output.
__global__ void k_loss(float* __restrict__ out) {
    int i = blockIdx.x;
    int tid = threadIdx.x;
    int w = tid >> 5, l = tid & 31;
    __shared__ float spc[256], spr[256];
    __shared__ float s_part[8];

    float cnt_i = g_cnt[i];
    bool valid_i = (cnt_i > 0.0f) && ((i % CO) != 0);
    float part = 0.0f;

    if (valid_i) {
        spc[tid] = g_sum_cur[i * C + tid];
        spr[tid] = g_sum_ref[i * C + tid];
        __syncthreads();

        float ac[8], ar[8];
#pragma unroll
        for (int q = 0; q < 8; ++q) {
            ac[q] = spc[l + 32 * q];
            ar[q] = spr[l + 32 * q];
        }
        // row-i inverse norms (every warp computes its own copy; xor-reduce -> all lanes)
        float sc = 0.0f, sr = 0.0f;
#pragma unroll
        for (int q = 0; q < 8; ++q) { sc += ac[q] * ac[q]; sr += ar[q] * ar[q]; }
#pragma unroll
        for (int o = 16; o; o >>= 1) {
            sc += __shfl_xor_sync(0xFFFFFFFFu, sc, o);
            sr += __shfl_xor_sync(0xFFFFFFFFu, sr, o);
        }
        float den_i = fmaxf(cnt_i, 1.0f);
        float rnc_i = 1.0f / fmaxf(sqrtf(sc), EPS * den_i);
        float rnr_i = 1.0f / fmaxf(sqrtf(sr), EPS * den_i);

        for (int j = w; j < NSEG; j += 8) {
            float cnt_j = g_cnt[j];
            if (!((cnt_j > 0.0f) && ((j % CO) != 0))) continue;
            const float* qc = g_sum_cur + j * C;
            const float* qr = g_sum_ref + j * C;
            float dc = 0.0f, dr = 0.0f, njc = 0.0f, njr = 0.0f;
#pragma unroll
            for (int q = 0; q < 8; ++q) {
                float xc = __ldg(qc + l + 32 * q);
                float xr = __ldg(qr + l + 32 * q);
                dc += ac[q] * xc;  njc += xc * xc;
                dr += ar[q] * xr;  njr += xr * xr;
            }
#pragma unroll
            for (int o = 16; o; o >>= 1) {
                dc  += __shfl_down_sync(0xFFFFFFFFu, dc,  o);
                dr  += __shfl_down_sync(0xFFFFFFFFu, dr,  o);
                njc += __shfl_down_sync(0xFFFFFFFFu, njc, o);
                njr += __shfl_down_sync(0xFFFFFFFFu, njr, o);
            }
            if (l == 0) {
                float den_j = fmaxf(cnt_j, 1.0f);
                float rnc_j = 1.0f / fmaxf(sqrtf(njc), EPS * den_j);
                float rnr_j = 1.0f / fmaxf(sqrtf(njr), EPS * den_j);
                float d = dc * rnc_i * rnc_j - dr * rnr_i * rnr_j;
                part += d * d;
            }
        }
    }

    if (l == 0) s_part[w] = part;
    __syncthreads();
    if (tid == 0) {
        float tot = 0.0f;
#pragma unroll
        for (int q = 0; q < 8; ++q) tot += s_part[q];
        if (tot != 0.0f) atomicAdd(&g_sq, tot);
        __threadfence();
        unsigned int t = atomicAdd(&g_ticket, 1u);
        if (t == NSEG - 1) {
            float k  = g_k;
            float sq = g_sq;
            out[0] = (k > 0.0f) ? (sq / fmaxf(k * k, 1.0f)) : 0.0f;
        }
    }
}

// ---------------- launch ----------------
extern "C" void kernel_launch(void* const* d_in, const int* in_sizes, int n_in,
                              void* d_out, int out_size) {
    // Resolve inputs by element count (robust to metadata ordering).
    const float* features     = nullptr;
    const float* features_old = nullptr;
    const float* outputs_old  = nullptr;
    const int*   labels       = nullptr;
    const int*   num_old      = nullptr;
    for (int i = 0; i < n_in; ++i) {
        int sz = in_sizes[i];
        if (sz == N_FEAT) {
            if (!features) features = (const float*)d_in[i];
            else           features_old = (const float*)d_in[i];
        } else if (sz == N_OUT) {
            outputs_old = (const float*)d_in[i];
        } else if (sz == N_LAB) {
            labels = (const int*)d_in[i];
        } else if (sz == 1) {
            num_old = (const int*)d_in[i];
        }
    }
    float* out = (float*)d_out;

    k_pseudo<<<dim3(HW / 256, B), 256>>>(outputs_old, labels, num_old);
    k_segsum<<<dim3(C + 1, B), 256>>>(features, features_old);
    k_loss<<<NSEG, 256>>>(out);
}